// round 4
// baseline (speedup 1.0000x reference)
#include <cuda_runtime.h>
#include <math.h>

#define BB 1024
#define TT 128
#define KK 128
#define STARTT 126
#define STOPP 127

typedef unsigned long long ull;

__device__ __forceinline__ ull addx2(ull a, ull b) {
    ull r;
    asm("add.rn.f32x2 %0, %1, %2;" : "=l"(r) : "l"(a), "l"(b));
    return r;
}
__device__ __forceinline__ float lo32(ull v) { return __uint_as_float((unsigned)v); }
__device__ __forceinline__ float hi32(ull v) { return __uint_as_float((unsigned)(v >> 32)); }
__device__ __forceinline__ ull packf2(float lo, float hi) {
    ull r;
    asm("mov.b64 %0, {%1, %2};" : "=l"(r) : "r"(__float_as_uint(lo)), "r"(__float_as_uint(hi)));
    return r;
}

// Thread layout: tid = cur*2 + half. Each thread scans 64 prevs ([64*half, 64*half+64)).
__global__ __launch_bounds__(256, 2)
void viterbi_kernel(const float* __restrict__ feats,
                    const float* __restrict__ trans,
                    const void*  __restrict__ masks,
                    float* __restrict__ out,
                    int score_off, int dec_off)
{
    __shared__ __align__(16) float part[2][KK];
    __shared__ float finv[KK];
    __shared__ int   dec_s[TT];
    __shared__ int   misc[8];
    __shared__ unsigned char bp[TT * KK];

    const int b    = blockIdx.x;
    const int tid  = threadIdx.x;
    const int cur  = tid >> 1;
    const int half = tid & 1;
    const int pofs = half << 6;         // prev offset: 0 or 64

    // ---- this thread's 64-prev slice of the trans column, packed f32x2 ----
    ull tv2[32];
    #pragma unroll
    for (int k = 0; k < 32; ++k) {
        float lo = trans[(pofs + 2 * k)     * KK + cur];
        float hi = trans[(pofs + 2 * k + 1) * KK + cur];
        tv2[k] = packf2(lo, hi);
    }

    // ---- sequence length (mask dtype auto-detected); threads 0..127 vote ----
    int m = 0;
    if (tid < TT) {
        unsigned w0 = *(const unsigned*)masks;
        if (w0 == 1u)                   m = ((const int*)masks)[b * TT + tid] != 0;
        else if (w0 == 0x3F800000u)     m = (((const float*)masks)[b * TT + tid] != 0.0f);
        else                            m = ((const unsigned char*)masks)[b * TT + tid] != 0;
    }
    unsigned bal = __ballot_sync(0xffffffffu, m);
    if ((tid & 31) == 0 && tid < TT) misc[tid >> 5] = __popc(bal);
    __syncthreads();
    const int len = misc[0] + misc[1] + misc[2] + misc[3];

    const float* fb = feats + (size_t)b * (TT * KK);

    // ---- t = 0 init ----
    if (tid < KK) part[0][tid] = fb[tid] + trans[STARTT * KK + tid];
    __syncthreads();

    // ---- Forward Viterbi ----
    float ft = fb[KK + cur];                        // feat for t=1, prefetched
    for (int t = 1; t < len; ++t) {
        const float* pbase = part[(t - 1) & 1] + pofs;
        const ulonglong2* pp2 = (const ulonglong2*)pbase;

        // Phase 1: pure max over 4 contiguous ranges of 16 prevs.
        float a[4];
        #pragma unroll
        for (int r = 0; r < 4; ++r) {
            ulonglong2 u0 = pp2[r * 4 + 0];
            ulonglong2 u1 = pp2[r * 4 + 1];
            ulonglong2 u2 = pp2[r * 4 + 2];
            ulonglong2 u3 = pp2[r * 4 + 3];
            ull s0 = addx2(u0.x, tv2[r * 8 + 0]);
            ull s1 = addx2(u0.y, tv2[r * 8 + 1]);
            ull s2 = addx2(u1.x, tv2[r * 8 + 2]);
            ull s3 = addx2(u1.y, tv2[r * 8 + 3]);
            ull s4 = addx2(u2.x, tv2[r * 8 + 4]);
            ull s5 = addx2(u2.y, tv2[r * 8 + 5]);
            ull s6 = addx2(u3.x, tv2[r * 8 + 6]);
            ull s7 = addx2(u3.y, tv2[r * 8 + 7]);
            float m0 = fmaxf(fmaxf(lo32(s0), hi32(s0)), fmaxf(lo32(s1), hi32(s1)));
            float m1 = fmaxf(fmaxf(lo32(s2), hi32(s2)), fmaxf(lo32(s3), hi32(s3)));
            float m2 = fmaxf(fmaxf(lo32(s4), hi32(s4)), fmaxf(lo32(s5), hi32(s5)));
            float m3 = fmaxf(fmaxf(lo32(s6), hi32(s6)), fmaxf(lo32(s7), hi32(s7)));
            a[r] = fmaxf(fmaxf(m0, m1), fmaxf(m2, m3));
        }
        float vbest = fmaxf(fmaxf(a[0], a[1]), fmaxf(a[2], a[3]));

        // First range achieving the local max (min-index, flat).
        int r0 = (a[0] == vbest) ? 0 : 4;
        int r1 = (a[1] == vbest) ? 1 : 4;
        int r2 = (a[2] == vbest) ? 2 : 4;
        int r3 = (a[3] == vbest) ? 3 : 4;
        int rsel = min(min(r0, r1), min(r2, r3));

        // Phase 2: rescan winning range from registers (tv2 4-way select) +
        // broadcast LDS of pp. addx2 on identical bits => bitwise-equal values.
        const ull* ppu = (const ull*)(pbase + (rsel << 4));
        int base = pofs + (rsel << 4);
        int idx = 255;
        #pragma unroll
        for (int k = 0; k < 8; ++k) {
            ull ta = (rsel & 2) ? tv2[16 + (rsel & 1) * 8 + k]
                                : tv2[(rsel & 1) * 8 + k];
            ull s = addx2(ppu[k], ta);
            int c0 = (lo32(s) == vbest) ? (base + 2 * k)     : 255;
            int c1 = (hi32(s) == vbest) ? (base + 2 * k + 1) : 255;
            idx = min(idx, min(c0, c1));
        }

        // Pair combine (half0 = prevs 0..63 wins ties).
        float ob = __shfl_xor_sync(0xffffffffu, vbest, 1);
        int   oi = __shfl_xor_sync(0xffffffffu, idx,   1);
        if (half == 0) {
            float g   = fmaxf(vbest, ob);
            int  gidx = (vbest >= ob) ? idx : oi;
            part[t & 1][cur] = g + ft;
            bp[t * KK + cur] = (unsigned char)gidx;
        }
        ft = fb[(t + 1) * KK + cur];   // prefetch next feat behind the barrier
        __syncthreads();
    }

    // ---- Transition to STOP from the last valid partition ----
    if (tid < KK) {
        const float* lp = part[(len - 1) & 1];
        finv[tid] = lp[tid] + trans[tid * KK + STOPP];
    }
    __syncthreads();

    if (tid == 0) {
        float bsc = finv[0];
        int ptr = 0;
        #pragma unroll 4
        for (int p = 1; p < KK; ++p) {
            float v = finv[p];
            if (v > bsc) { bsc = v; ptr = p; }
        }
        misc[4] = ptr;
        misc[5] = __float_as_int(bsc);
        dec_s[len - 1] = ptr;
        int q = ptr;
        for (int t = len - 1; t >= 1; --t) {
            q = bp[t * KK + q];
            dec_s[t - 1] = q;
        }
    }
    __syncthreads();

    if (tid < TT) {
        const int ptr = misc[4];
        int val;
        if (tid < len)          val = dec_s[tid];
        else if (tid == TT - 1) val = ptr;
        else                    val = 0;
        if (dec_off >= 0)  out[dec_off + b * TT + tid] = (float)val;
        if (score_off >= 0 && tid == 0) out[score_off + b] = __int_as_float(misc[5]);
    }
}

extern "C" void kernel_launch(void* const* d_in, const int* in_sizes, int n_in,
                              void* d_out, int out_size) {
    const float* feats = nullptr;
    const float* trans = nullptr;
    const void*  masks = nullptr;
    for (int i = 0; i < n_in; ++i) {
        if      (in_sizes[i] == BB * TT * KK) feats = (const float*)d_in[i];
        else if (in_sizes[i] == KK * KK)      trans = (const float*)d_in[i];
        else                                  masks = d_in[i];
    }

    int score_off, dec_off;
    if      (out_size == BB * TT + BB) { score_off = 0;  dec_off = BB; }
    else if (out_size == BB * TT)      { score_off = -1; dec_off = 0;  }
    else if (out_size == BB)           { score_off = 0;  dec_off = -1; }
    else                               { score_off = 0;  dec_off = BB; }

    viterbi_kernel<<<BB, 256>>>(feats, trans, masks,
                                (float*)d_out, score_off, dec_off);
}

// round 5
// speedup vs baseline: 1.0022x; 1.0022x over previous
#include <cuda_runtime.h>
#include <math.h>

#define BB 1024
#define TT 128
#define KK 128
#define STARTT 126
#define STOPP 127

typedef unsigned long long ull;

__device__ __forceinline__ ull addx2(ull a, ull b) {
    ull r;
    asm("add.rn.f32x2 %0, %1, %2;" : "=l"(r) : "l"(a), "l"(b));
    return r;
}
__device__ __forceinline__ float lo32(ull v) { return __uint_as_float((unsigned)v); }
__device__ __forceinline__ float hi32(ull v) { return __uint_as_float((unsigned)(v >> 32)); }
__device__ __forceinline__ ull packf2(float lo, float hi) {
    ull r;
    asm("mov.b64 %0, {%1, %2};" : "=l"(r) : "r"(__float_as_uint(lo)), "r"(__float_as_uint(hi)));
    return r;
}

// Thread layout: tid = cur*2 + half. Each thread scans 64 prevs ([64*half, 64*half+64)).
__global__ __launch_bounds__(256, 2)
void viterbi_kernel(const float* __restrict__ feats,
                    const float* __restrict__ trans,
                    const void*  __restrict__ masks,
                    float* __restrict__ out,
                    int score_off, int dec_off)
{
    __shared__ __align__(16) float part[2][KK];
    __shared__ float finv[KK];
    __shared__ int   dec_s[TT];
    __shared__ int   misc[8];
    __shared__ unsigned char bp[TT * KK];

    const int b    = blockIdx.x;
    const int tid  = threadIdx.x;
    const int cur  = tid >> 1;
    const int half = tid & 1;
    const int pofs = half << 6;         // prev offset: 0 or 64

    // ---- this thread's 64-prev slice of the trans column, packed f32x2 ----
    ull tv2[32];
    #pragma unroll
    for (int k = 0; k < 32; ++k) {
        float lo = trans[(pofs + 2 * k)     * KK + cur];
        float hi = trans[(pofs + 2 * k + 1) * KK + cur];
        tv2[k] = packf2(lo, hi);
    }

    // ---- sequence length (mask dtype auto-detected); threads 0..127 vote ----
    int m = 0;
    if (tid < TT) {
        unsigned w0 = *(const unsigned*)masks;
        if (w0 == 1u)                   m = ((const int*)masks)[b * TT + tid] != 0;
        else if (w0 == 0x3F800000u)     m = (((const float*)masks)[b * TT + tid] != 0.0f);
        else                            m = ((const unsigned char*)masks)[b * TT + tid] != 0;
    }
    unsigned bal = __ballot_sync(0xffffffffu, m);
    if ((tid & 31) == 0 && tid < TT) misc[tid >> 5] = __popc(bal);
    __syncthreads();
    const int len = misc[0] + misc[1] + misc[2] + misc[3];

    const float* fb = feats + (size_t)b * (TT * KK);

    // ---- t = 0 init ----
    if (tid < KK) part[0][tid] = fb[tid] + trans[STARTT * KK + tid];
    __syncthreads();

    // ---- Forward Viterbi ----
    float ft = fb[KK + cur];                        // feat for t=1, prefetched
    for (int t = 1; t < len; ++t) {
        const float* pbase = part[(t - 1) & 1] + pofs;
        const ulonglong2* pp2 = (const ulonglong2*)pbase;

        // Phase 1: pure max over 4 contiguous ranges of 16 prevs.
        float a[4];
        #pragma unroll
        for (int r = 0; r < 4; ++r) {
            ulonglong2 u0 = pp2[r * 4 + 0];
            ulonglong2 u1 = pp2[r * 4 + 1];
            ulonglong2 u2 = pp2[r * 4 + 2];
            ulonglong2 u3 = pp2[r * 4 + 3];
            ull s0 = addx2(u0.x, tv2[r * 8 + 0]);
            ull s1 = addx2(u0.y, tv2[r * 8 + 1]);
            ull s2 = addx2(u1.x, tv2[r * 8 + 2]);
            ull s3 = addx2(u1.y, tv2[r * 8 + 3]);
            ull s4 = addx2(u2.x, tv2[r * 8 + 4]);
            ull s5 = addx2(u2.y, tv2[r * 8 + 5]);
            ull s6 = addx2(u3.x, tv2[r * 8 + 6]);
            ull s7 = addx2(u3.y, tv2[r * 8 + 7]);
            float m0 = fmaxf(fmaxf(lo32(s0), hi32(s0)), fmaxf(lo32(s1), hi32(s1)));
            float m1 = fmaxf(fmaxf(lo32(s2), hi32(s2)), fmaxf(lo32(s3), hi32(s3)));
            float m2 = fmaxf(fmaxf(lo32(s4), hi32(s4)), fmaxf(lo32(s5), hi32(s5)));
            float m3 = fmaxf(fmaxf(lo32(s6), hi32(s6)), fmaxf(lo32(s7), hi32(s7)));
            a[r] = fmaxf(fmaxf(m0, m1), fmaxf(m2, m3));
        }
        float vbest = fmaxf(fmaxf(a[0], a[1]), fmaxf(a[2], a[3]));

        // First range achieving the local max (min-index, flat).
        int r0 = (a[0] == vbest) ? 0 : 4;
        int r1 = (a[1] == vbest) ? 1 : 4;
        int r2 = (a[2] == vbest) ? 2 : 4;
        int r3 = (a[3] == vbest) ? 3 : 4;
        int rsel = min(min(r0, r1), min(r2, r3));

        // Phase 2: rescan winning range from registers (tv2 4-way select) +
        // broadcast LDS of pp. addx2 on identical bits => bitwise-equal values.
        const ull* ppu = (const ull*)(pbase + (rsel << 4));
        int base = pofs + (rsel << 4);
        int idx = 255;
        #pragma unroll
        for (int k = 0; k < 8; ++k) {
            ull ta = (rsel & 2) ? tv2[16 + (rsel & 1) * 8 + k]
                                : tv2[(rsel & 1) * 8 + k];
            ull s = addx2(ppu[k], ta);
            int c0 = (lo32(s) == vbest) ? (base + 2 * k)     : 255;
            int c1 = (hi32(s) == vbest) ? (base + 2 * k + 1) : 255;
            idx = min(idx, min(c0, c1));
        }

        // Pair combine (half0 = prevs 0..63 wins ties).
        float ob = __shfl_xor_sync(0xffffffffu, vbest, 1);
        int   oi = __shfl_xor_sync(0xffffffffu, idx,   1);
        if (half == 0) {
            float g   = fmaxf(vbest, ob);
            int  gidx = (vbest >= ob) ? idx : oi;
            part[t & 1][cur] = g + ft;
            bp[t * KK + cur] = (unsigned char)gidx;
        }
        ft = fb[(t + 1) * KK + cur];   // prefetch next feat behind the barrier
        __syncthreads();
    }

    // ---- Transition to STOP from the last valid partition ----
    if (tid < KK) {
        const float* lp = part[(len - 1) & 1];
        finv[tid] = lp[tid] + trans[tid * KK + STOPP];
    }
    __syncthreads();

    if (tid == 0) {
        float bsc = finv[0];
        int ptr = 0;
        #pragma unroll 4
        for (int p = 1; p < KK; ++p) {
            float v = finv[p];
            if (v > bsc) { bsc = v; ptr = p; }
        }
        misc[4] = ptr;
        misc[5] = __float_as_int(bsc);
        dec_s[len - 1] = ptr;
        int q = ptr;
        for (int t = len - 1; t >= 1; --t) {
            q = bp[t * KK + q];
            dec_s[t - 1] = q;
        }
    }
    __syncthreads();

    if (tid < TT) {
        const int ptr = misc[4];
        int val;
        if (tid < len)          val = dec_s[tid];
        else if (tid == TT - 1) val = ptr;
        else                    val = 0;
        if (dec_off >= 0)  out[dec_off + b * TT + tid] = (float)val;
        if (score_off >= 0 && tid == 0) out[score_off + b] = __int_as_float(misc[5]);
    }
}

extern "C" void kernel_launch(void* const* d_in, const int* in_sizes, int n_in,
                              void* d_out, int out_size) {
    const float* feats = nullptr;
    const float* trans = nullptr;
    const void*  masks = nullptr;
    for (int i = 0; i < n_in; ++i) {
        if      (in_sizes[i] == BB * TT * KK) feats = (const float*)d_in[i];
        else if (in_sizes[i] == KK * KK)      trans = (const float*)d_in[i];
        else                                  masks = d_in[i];
    }

    int score_off, dec_off;
    if      (out_size == BB * TT + BB) { score_off = 0;  dec_off = BB; }
    else if (out_size == BB * TT)      { score_off = -1; dec_off = 0;  }
    else if (out_size == BB)           { score_off = 0;  dec_off = -1; }
    else                               { score_off = 0;  dec_off = BB; }

    viterbi_kernel<<<BB, 256>>>(feats, trans, masks,
                                (float*)d_out, score_off, dec_off);
}